// round 9
// baseline (speedup 1.0000x reference)
#include <cuda_runtime.h>
#include <cuda_fp16.h>
#include <cstdint>

#define N_TOK 16384
#define DIM   1024
#define NEXP  16
#define HID   4096

// ---------------- device scratch (no allocations allowed) ----------------
__device__ int    g_counts[NEXP];
__device__ int    g_perm [NEXP * N_TOK];
__device__ float  g_gatev[NEXP * N_TOK];
__device__ __half g_xh [(size_t)N_TOK * DIM];          // x  rounded to fp16
__device__ __half g_w1h[(size_t)NEXP * DIM * HID];     // W1 rounded to fp16

// ---------------- helpers ----------------
__device__ __forceinline__ uint32_t smem_u32(const void* p) {
    uint32_t a;
    asm("{ .reg .u64 t; cvta.to.shared.u64 t, %1; cvt.u32.u64 %0, t; }" : "=r"(a) : "l"(p));
    return a;
}
#define CP_ASYNC16(dst, src) \
    asm volatile("cp.async.cg.shared.global [%0], [%1], 16;" :: "r"(dst), "l"(src) : "memory")
#define CP_COMMIT() asm volatile("cp.async.commit_group;" ::: "memory")
#define CP_WAIT(n)  asm volatile("cp.async.wait_group %0;" :: "n"(n) : "memory")

#define LDSM4(r, a) \
    asm volatile("ldmatrix.sync.aligned.m8n8.x4.shared.b16 {%0,%1,%2,%3}, [%4];" \
        : "=r"((r)[0]), "=r"((r)[1]), "=r"((r)[2]), "=r"((r)[3]) : "r"(a))
#define LDSM4T(r, a) \
    asm volatile("ldmatrix.sync.aligned.m8n8.x4.trans.shared.b16 {%0,%1,%2,%3}, [%4];" \
        : "=r"((r)[0]), "=r"((r)[1]), "=r"((r)[2]), "=r"((r)[3]) : "r"(a))

__device__ __forceinline__ void mma_f16(float* c, const uint32_t* a, const uint32_t* b) {
    asm volatile(
        "mma.sync.aligned.m16n8k16.row.col.f32.f16.f16.f32 "
        "{%0,%1,%2,%3}, {%4,%5,%6,%7}, {%8,%9}, {%0,%1,%2,%3};"
        : "+f"(c[0]), "+f"(c[1]), "+f"(c[2]), "+f"(c[3])
        : "r"(a[0]), "r"(a[1]), "r"(a[2]), "r"(a[3]), "r"(b[0]), "r"(b[1]));
}

// ---------------- kernel 0: zero counts ----------------
__global__ void zero_counts_kernel() {
    if (threadIdx.x < NEXP) g_counts[threadIdx.x] = 0;
}

// ---------------- kernel 1: fp16-round a buffer ----------------
__global__ __launch_bounds__(256) void to_half_kernel(const float4* __restrict__ src,
                                                      __half2* __restrict__ dst) {
    size_t i = (size_t)blockIdx.x * 256 + threadIdx.x;
    float4 v = src[i];
    dst[2 * i]     = __floats2half2_rn(v.x, v.y);
    dst[2 * i + 1] = __floats2half2_rn(v.z, v.w);
}

// ---------------- kernel 2: router (fp32 exact), 32 tokens/CTA ----------------
__global__ __launch_bounds__(256) void router_kernel(
    const float* __restrict__ x,
    const float* __restrict__ Wn,
    const float* __restrict__ bn,
    float* __restrict__ out)
{
    __shared__ float Xs[32][33];    // [d][token]
    __shared__ float Ws[32][16];    // [d][expert]

    const int tid  = threadIdx.x;
    const int tx   = tid & 15;      // expert lane
    const int g    = tid >> 4;      // token sub-group 0..15
    const int tok0 = blockIdx.x * 32;

    float acc[2] = {0.f, 0.f};

    for (int dk = 0; dk < DIM; dk += 32) {
        {
            int t  = tid >> 3;
            int d4 = (tid & 7) * 4;
            float4 v = *(const float4*)(x + (size_t)(tok0 + t) * DIM + dk + d4);
            Xs[d4 + 0][t] = v.x;
            Xs[d4 + 1][t] = v.y;
            Xs[d4 + 2][t] = v.z;
            Xs[d4 + 3][t] = v.w;
        }
        {
            int idx = tid * 2;
            int d = idx >> 4, ee = idx & 15;
            float2 w = *(const float2*)(Wn + (size_t)(dk + d) * NEXP + ee);
            Ws[d][ee]     = w.x;
            Ws[d][ee + 1] = w.y;
        }
        __syncthreads();
#pragma unroll
        for (int kk = 0; kk < 32; kk++) {
            float wv = Ws[kk][tx];
            acc[0] += Xs[kk][g]      * wv;
            acc[1] += Xs[kk][g + 16] * wv;
        }
        __syncthreads();
    }

    const float bb = bn[tx];
#pragma unroll
    for (int i = 0; i < 2; i++) {
        float v0 = acc[i] + bb;
        int   i0 = tx;
        float v1 = -3.4e38f;
        int   i1 = NEXP;
#pragma unroll
        for (int off = 8; off >= 1; off >>= 1) {
            float ov0 = __shfl_xor_sync(0xffffffffu, v0, off);
            int   oi0 = __shfl_xor_sync(0xffffffffu, i0, off);
            float ov1 = __shfl_xor_sync(0xffffffffu, v1, off);
            int   oi1 = __shfl_xor_sync(0xffffffffu, i1, off);
            bool other_first = (ov0 > v0) || (ov0 == v0 && oi0 < i0);
            float n0, n1; int m0, m1;
            if (other_first) {
                n0 = ov0; m0 = oi0;
                if (v0 > ov1 || (v0 == ov1 && i0 < oi1)) { n1 = v0;  m1 = i0;  }
                else                                     { n1 = ov1; m1 = oi1; }
            } else {
                n0 = v0; m0 = i0;
                if (ov0 > v1 || (ov0 == v1 && oi0 < i1)) { n1 = ov0; m1 = oi0; }
                else                                     { n1 = v1;  m1 = i1;  }
            }
            v0 = n0; i0 = m0; v1 = n1; i1 = m1;
        }
        if (tx == 0) {
            int token = tok0 + g + 16 * i;
            float e1  = __expf(v1 - v0);
            float inv = 1.f / (1.f + e1);
            int p0 = atomicAdd(&g_counts[i0], 1);
            g_perm [i0 * N_TOK + p0] = token;
            g_gatev[i0 * N_TOK + p0] = inv;
            int p1 = atomicAdd(&g_counts[i1], 1);
            g_perm [i1 * N_TOK + p1] = token;
            g_gatev[i1 * N_TOK + p1] = e1 * inv;
            out[token] = 0.f;
        }
    }
}

// ---------------- kernel 3: fp16 mma expert GEMM, H-sliced ----------------
// CTA = (128-token tile, expert, H-slice of 512). 8 warps 2x4, warp tile 64x64.
// 64 tiles = 2 H-chunks(256) x 32 K-steps(32). 6-stage cp.async pipeline in
// 2-tile groups, CP_WAIT(1) + one __syncthreads per group. ldmatrix frags.
// Fused relu(+b1)*W2 epilogue at H-chunk boundaries.
#define AS_H 40                 // A smem row stride in halfs (32 + 8 pad)
#define BS_H 264                // B smem row stride in halfs (256 + 8 pad)
#define A_TILE_B (128 * AS_H * 2)     // 10240 bytes per A buffer
#define B_TILE_B (32 * BS_H * 2)      // 16896 bytes per B buffer
#define NBUF 6
#define SM_B1_B   (NBUF * (A_TILE_B + B_TILE_B))    // 162816
#define SM_W2_B   (SM_B1_B + 2048)
#define SM_TOK_B  (SM_W2_B + 2048)
#define SM_GTS_B  (SM_TOK_B + 512)
#define SM_RED_B  (SM_GTS_B + 512)
#define MOE_SMEM_BYTES (SM_RED_B + 2048)

__global__ __launch_bounds__(256, 1) void moe_mma_kernel(
    const float* __restrict__ b1,
    const float* __restrict__ W2,
    const float* __restrict__ b2,
    float* __restrict__ out)
{
    const int e     = blockIdx.y;
    const int cnt   = g_counts[e];
    const int tbase = blockIdx.x * 128;
    if (tbase >= cnt) return;
    const int slice = blockIdx.z;           // 0..7, 512 H cols each

    extern __shared__ char sm[];
    __half* As    = (__half*)sm;                          // NBUF buffers
    __half* Bs    = (__half*)(sm + NBUF * A_TILE_B);      // NBUF buffers
    float* b1s    = (float*)(sm + SM_B1_B);
    float* w2s    = (float*)(sm + SM_W2_B);
    int*   toks_s = (int*)  (sm + SM_TOK_B);
    float* gts_s  = (float*)(sm + SM_GTS_B);
    float* red_s  = (float*)(sm + SM_RED_B);   // [128][4]

    const int tid  = threadIdx.x;
    const int wid  = tid >> 5;
    const int lane = tid & 31;
    const int wy   = wid >> 2;              // 0..1 (m block 64)
    const int wx   = wid & 3;               // 0..3 (n block 64)
    const int r_   = lane >> 2;             // 0..7
    const int c_   = lane & 3;              // 0..3

    const int nbase = slice * 512;
    if (tid < 128) {
        int idx = tbase + tid;
        int t = 0; float gv = 0.f;
        if (idx < cnt) { t = g_perm[e * N_TOK + idx]; gv = g_gatev[e * N_TOK + idx]; }
        toks_s[tid] = t;
        gts_s[tid]  = gv;
    }
    {
        const float* b1e = b1 + (size_t)e * HID + nbase;
        const float* w2e = W2 + (size_t)e * HID + nbase;
        b1s[tid]       = b1e[tid];
        b1s[tid + 256] = b1e[tid + 256];
        w2s[tid]       = w2e[tid];
        w2s[tid + 256] = w2e[tid + 256];
    }
    __syncthreads();

    // ---- cp.async loader setup ----
    const __half* a_src = g_xh + (size_t)toks_s[tid >> 1] * DIM + (tid & 1) * 16;
    const uint32_t a_dst0 = smem_u32(As) + ((uint32_t)(tid >> 1) * AS_H + (tid & 1) * 16) * 2;
    const __half* b_src = g_w1h + (size_t)e * DIM * HID + (size_t)(tid >> 3) * HID
                        + nbase + (tid & 7) * 8;
    const uint32_t b_dst0 = smem_u32(Bs) + ((uint32_t)(tid >> 3) * BS_H + (tid & 7) * 8) * 2;

    // ---- ldmatrix base addresses (lane-dependent) ----
    const uint32_t a_lm = smem_u32(As)
        + (((uint32_t)(wy * 64 + (lane & 15)) * AS_H) + (uint32_t)(lane >> 4) * 8) * 2;
    const uint32_t b_lm = smem_u32(Bs)
        + (((uint32_t)(lane & 15) * BS_H) + (uint32_t)(wx * 64) + (uint32_t)(lane >> 4) * 8) * 2;

    float sacc[4][2];
#pragma unroll
    for (int mi = 0; mi < 4; mi++) { sacc[mi][0] = 0.f; sacc[mi][1] = 0.f; }

    float C[4][8][4];
#pragma unroll
    for (int mi = 0; mi < 4; mi++)
#pragma unroll
        for (int ni = 0; ni < 8; ni++)
#pragma unroll
            for (int q = 0; q < 4; q++) C[mi][ni][q] = 0.f;

    // tile j (0..63): hc = j>>5 (H-chunk of 256), kt = j&31 (d-step of 32), buf j%NBUF
#define LOAD_TILE(j) do {                                                         \
        const int   _kt = (j) & 31;                                               \
        const int   _hc = (j) >> 5;                                               \
        const int   _bf = (j) % NBUF;                                             \
        const __half* _as = a_src + _kt * 32;                                     \
        const __half* _bs = b_src + (size_t)_kt * (32 * HID) + _hc * 256;         \
        uint32_t _ad = a_dst0 + (uint32_t)_bf * A_TILE_B;                         \
        uint32_t _bd = b_dst0 + (uint32_t)_bf * B_TILE_B;                         \
        CP_ASYNC16(_ad,      _as);                                                \
        CP_ASYNC16(_ad + 16, _as + 8);                                            \
        CP_ASYNC16(_bd,       _bs);                                               \
        CP_ASYNC16(_bd + 128, _bs + 64);                                          \
        CP_ASYNC16(_bd + 256, _bs + 128);                                         \
        CP_ASYNC16(_bd + 384, _bs + 192);                                         \
    } while (0)

#define COMPUTE_TILE(it) do {                                                     \
        const uint32_t abuf = a_lm + (uint32_t)((it) % NBUF) * A_TILE_B;          \
        const uint32_t bbuf = b_lm + (uint32_t)((it) % NBUF) * B_TILE_B;          \
        _Pragma("unroll")                                                         \
        for (int s = 0; s < 2; s++) {                                             \
            uint32_t af[4][4];                                                    \
            _Pragma("unroll")                                                     \
            for (int mi = 0; mi < 4; mi++)                                        \
                LDSM4(af[mi], abuf + (uint32_t)(mi * 16 * AS_H + s * 16) * 2);    \
            uint32_t bf[4][4];                                                    \
            _Pragma("unroll")                                                     \
            for (int p = 0; p < 4; p++)                                           \
                LDSM4T(bf[p], bbuf + (uint32_t)(s * 16 * BS_H + p * 16) * 2);     \
            _Pragma("unroll")                                                     \
            for (int mi = 0; mi < 4; mi++)                                        \
                _Pragma("unroll")                                                 \
                for (int p = 0; p < 4; p++) {                                     \
                    mma_f16(C[mi][2 * p],     af[mi], &bf[p][0]);                 \
                    mma_f16(C[mi][2 * p + 1], af[mi], &bf[p][2]);                 \
                }                                                                 \
        }                                                                         \
        if (((it) & 31) == 31) {                                                  \
            const int hb = ((it) >> 5) * 256;                                     \
            _Pragma("unroll")                                                     \
            for (int mi = 0; mi < 4; mi++) {                                      \
                _Pragma("unroll")                                                 \
                for (int ni = 0; ni < 8; ni++) {                                  \
                    const int nl = hb + wx * 64 + ni * 8 + 2 * c_;                \
                    float2 bb = *(const float2*)&b1s[nl];                         \
                    float2 ww = *(const float2*)&w2s[nl];                         \
                    sacc[mi][0] += fmaxf(C[mi][ni][0] + bb.x, 0.f) * ww.x         \
                                 + fmaxf(C[mi][ni][1] + bb.y, 0.f) * ww.y;        \
                    sacc[mi][1] += fmaxf(C[mi][ni][2] + bb.x, 0.f) * ww.x         \
                                 + fmaxf(C[mi][ni][3] + bb.y, 0.f) * ww.y;        \
                    C[mi][ni][0] = 0.f; C[mi][ni][1] = 0.f;                       \
                    C[mi][ni][2] = 0.f; C[mi][ni][3] = 0.f;                       \
                }                                                                 \
            }                                                                     \
        }                                                                         \
    } while (0)

    // prologue: groups 0 and 1 (tiles 0..3)
    LOAD_TILE(0); LOAD_TILE(1); CP_COMMIT();
    LOAD_TILE(2); LOAD_TILE(3); CP_COMMIT();

    for (int j = 0; j < 32; j++) {
        const int i0 = 2 * j;
        CP_WAIT(1);            // group j complete (group j+1 may be in flight)
        __syncthreads();
        if (i0 + 4 < 64) {
            LOAD_TILE(i0 + 4);
            LOAD_TILE(i0 + 5);
        }
        CP_COMMIT();
        COMPUTE_TILE(i0);
        COMPUTE_TILE(i0 + 1);
    }

    // ---- reduce: fold 4 c-lanes (shfl), then 4 warp columns (smem) ----
#pragma unroll
    for (int mi = 0; mi < 4; mi++)
#pragma unroll
        for (int j = 0; j < 2; j++) {
            float v = sacc[mi][j];
            v += __shfl_xor_sync(0xffffffffu, v, 1);
            v += __shfl_xor_sync(0xffffffffu, v, 2);
            sacc[mi][j] = v;
        }
    __syncthreads();
    if (c_ == 0) {
#pragma unroll
        for (int mi = 0; mi < 4; mi++) {
            red_s[(wy * 64 + mi * 16 + r_) * 4 + wx]     = sacc[mi][0];
            red_s[(wy * 64 + mi * 16 + r_ + 8) * 4 + wx] = sacc[mi][1];
        }
    }
    __syncthreads();

    if (tid < 128) {
        float tot = red_s[tid * 4] + red_s[tid * 4 + 1]
                  + red_s[tid * 4 + 2] + red_s[tid * 4 + 3];
        int idx = tbase + tid;
        if (idx < cnt) {
            if (slice == 0) tot += b2[e];
            atomicAdd(out + toks_s[tid], gts_s[tid] * tot);
        }
    }
}

// ---------------- launch ----------------
extern "C" void kernel_launch(void* const* d_in, const int* in_sizes, int n_in,
                              void* d_out, int out_size) {
    const float* x  = (const float*)d_in[0];
    const float* Wn = (const float*)d_in[3];
    const float* bn = (const float*)d_in[4];
    const float* W1 = (const float*)d_in[5];
    const float* b1 = (const float*)d_in[6];
    const float* W2 = (const float*)d_in[7];
    const float* b2 = (const float*)d_in[8];
    float* out = (float*)d_out;

    __half* xh;  cudaGetSymbolAddress((void**)&xh,  g_xh);
    __half* w1h; cudaGetSymbolAddress((void**)&w1h, g_w1h);

    // one-time resource setup (host-side only; identical device work every call)
    static cudaStream_t s2 = nullptr;
    static cudaEvent_t  evF = nullptr, evJ = nullptr;
    if (s2 == nullptr) {
        cudaStreamCreateWithFlags(&s2, cudaStreamNonBlocking);
        cudaEventCreateWithFlags(&evF, cudaEventDisableTiming);
        cudaEventCreateWithFlags(&evJ, cudaEventDisableTiming);
        cudaFuncSetAttribute(moe_mma_kernel,
                             cudaFuncAttributeMaxDynamicSharedMemorySize, MOE_SMEM_BYTES);
    }

    // fork: W1 conversion (DRAM-floor 63us) alone on s2; everything else on main
    cudaEventRecord(evF, 0);
    cudaStreamWaitEvent(s2, evF, 0);
    to_half_kernel<<<((size_t)NEXP * DIM * HID / 4) / 256, 256, 0, s2>>>(
        (const float4*)W1, (__half2*)w1h);

    zero_counts_kernel<<<1, 32>>>();
    to_half_kernel<<<(N_TOK * DIM / 4) / 256, 256>>>((const float4*)x, (__half2*)xh);
    router_kernel<<<N_TOK / 32, 256>>>(x, Wn, bn, out);

    // join: moe needs router output AND the W1 conversion
    cudaEventRecord(evJ, s2);
    cudaStreamWaitEvent(0, evJ, 0);
    moe_mma_kernel<<<dim3(128, NEXP, 8), 256, MOE_SMEM_BYTES>>>(b1, W2, b2, out);
}